// round 13
// baseline (speedup 1.0000x reference)
#include <cuda_runtime.h>
#include <cuda_bf16.h>
#include <cuda_fp16.h>
#include <math.h>
#include <stdint.h>

#define NN    50000
#define IND   128
#define OUTD  32
#define NHEAD 8
#define EE    800000
#define FF    256      // OUTD*NHEAD
#define SEMH  128
#define MT    ((NN + 127) / 128)   // 391 M-tiles
#define NB    98                   // M-chunks per ntile/path CTA column
#define HB    196                  // hist blocks inside hist_prep
#define PB    512                  // prep blocks inside hist_prep
#define SCB   196                  // scatter chunk-blocks inside gemm launch

// ---------------- scratch (device globals: allocation-free rule) ------------
__device__ __half g_fh_a[NN * FF];     // feat fp16 (gather payload)
__device__ __half g_fh_b[NN * FF];
__device__ __half g_zh_a[NN * FF];     // z fp16
__device__ __half g_zh_b[NN * FF];
__device__ float g_el_a[NN * NHEAD];
__device__ float g_er_a[NN * NHEAD];
__device__ float g_el_b[NN * NHEAD];
__device__ float g_er_b[NN * NHEAD];
__device__ int   g_cnt[2][NN];         // zero at load; scan re-zeroes each run
__device__ int   g_off[2][NN + 1];
__device__ int   g_cur[2][NN];
__device__ int   g_csrc[2][EE];
__device__ float g_qsum[2];
// pre-split inputs
__device__ __nv_bfloat16 g_h_hi[NN * IND];
__device__ __nv_bfloat16 g_h_lo[NN * IND];
__device__ __nv_bfloat16 g_wt_hi[2][FF * IND];
__device__ __nv_bfloat16 g_wt_lo[2][FF * IND];
__device__ __half g_wsemt[SEMH * FF];  // fp16 Wsem^T

// ==================== helpers ===============================================
__device__ __forceinline__ uint32_t smem_u32(const void* p) {
    uint32_t a;
    asm("{ .reg .u64 t; cvta.to.shared.u64 t, %1; cvt.u32.u64 %0, t; }"
        : "=r"(a) : "l"(p));
    return a;
}
__device__ __forceinline__ void ldsm_x4(uint32_t& r0, uint32_t& r1,
                                        uint32_t& r2, uint32_t& r3, uint32_t addr) {
    asm volatile("ldmatrix.sync.aligned.m8n8.x4.shared.b16 {%0,%1,%2,%3}, [%4];"
                 : "=r"(r0), "=r"(r1), "=r"(r2), "=r"(r3) : "r"(addr));
}
__device__ __forceinline__ void mma16816_bf(float* d, const uint32_t* a, const uint32_t* b) {
    asm volatile(
        "mma.sync.aligned.m16n8k16.row.col.f32.bf16.bf16.f32 "
        "{%0,%1,%2,%3}, {%4,%5,%6,%7}, {%8,%9}, {%0,%1,%2,%3};"
        : "+f"(d[0]), "+f"(d[1]), "+f"(d[2]), "+f"(d[3])
        : "r"(a[0]), "r"(a[1]), "r"(a[2]), "r"(a[3]), "r"(b[0]), "r"(b[1]));
}
__device__ __forceinline__ void mma16816_f16(float* d, const uint32_t* a, const uint32_t* b) {
    asm volatile(
        "mma.sync.aligned.m16n8k16.row.col.f32.f16.f16.f32 "
        "{%0,%1,%2,%3}, {%4,%5,%6,%7}, {%8,%9}, {%0,%1,%2,%3};"
        : "+f"(d[0]), "+f"(d[1]), "+f"(d[2]), "+f"(d[3])
        : "r"(a[0]), "r"(a[1]), "r"(a[2]), "r"(a[3]), "r"(b[0]), "r"(b[1]));
}
__device__ __forceinline__ float tanh_fast(float x) {
    float y; asm("tanh.approx.f32 %0, %1;" : "=f"(y) : "f"(x)); return y;
}
// packed f32x2 FMA accumulate of 8 dims (4 pairs) — saves 4 issue slots/edge
__device__ __forceinline__ void fma8x2(uint64_t* acc2, uint64_t wp, const uint4& v) {
    float2 f0 = __half22float2(*(__half2*)&v.x);
    float2 f1 = __half22float2(*(__half2*)&v.y);
    float2 f2 = __half22float2(*(__half2*)&v.z);
    float2 f3 = __half22float2(*(__half2*)&v.w);
    uint64_t p0, p1, p2, p3;
    asm("mov.b64 %0, {%1,%2};" : "=l"(p0) : "f"(f0.x), "f"(f0.y));
    asm("mov.b64 %0, {%1,%2};" : "=l"(p1) : "f"(f1.x), "f"(f1.y));
    asm("mov.b64 %0, {%1,%2};" : "=l"(p2) : "f"(f2.x), "f"(f2.y));
    asm("mov.b64 %0, {%1,%2};" : "=l"(p3) : "f"(f3.x), "f"(f3.y));
    asm("fma.rn.f32x2 %0, %1, %2, %0;" : "+l"(acc2[0]) : "l"(wp), "l"(p0));
    asm("fma.rn.f32x2 %0, %1, %2, %0;" : "+l"(acc2[1]) : "l"(wp), "l"(p1));
    asm("fma.rn.f32x2 %0, %1, %2, %0;" : "+l"(acc2[2]) : "l"(wp), "l"(p2));
    asm("fma.rn.f32x2 %0, %1, %2, %0;" : "+l"(acc2[3]) : "l"(wp), "l"(p3));
}
__device__ __forceinline__ uint64_t dup_f32x2(float w) {
    uint64_t wp;
    asm("mov.b64 %0, {%1,%1};" : "=l"(wp) : "f"(w));
    return wp;
}

// ---------------- K1: hist (blocks 0..HB-1) + prep (blocks HB..HB+PB-1) -----
__global__ void hist_prep_kernel(const int* __restrict__ dst_a,
                                 const int* __restrict__ dst_b,
                                 const float* __restrict__ hsrc,
                                 const float* __restrict__ W_a,
                                 const float* __restrict__ W_b,
                                 const float* __restrict__ Wsem) {
    if (blockIdx.x < HB) {
        int t = blockIdx.x * blockDim.x + threadIdx.x;
        const int T = HB * 256;
        for (int base = t; base < EE; base += 4 * T) {
            int j0 = base, j1 = base + T, j2 = base + 2 * T, j3 = base + 3 * T;
            int da0 = dst_a[j0];
            int da1 = j1 < EE ? dst_a[j1] : -1;
            int da2 = j2 < EE ? dst_a[j2] : -1;
            int da3 = j3 < EE ? dst_a[j3] : -1;
            int db0 = dst_b[j0];
            int db1 = j1 < EE ? dst_b[j1] : -1;
            int db2 = j2 < EE ? dst_b[j2] : -1;
            int db3 = j3 < EE ? dst_b[j3] : -1;
            atomicAdd(&g_cnt[0][da0], 1);
            if (da1 >= 0) atomicAdd(&g_cnt[0][da1], 1);
            if (da2 >= 0) atomicAdd(&g_cnt[0][da2], 1);
            if (da3 >= 0) atomicAdd(&g_cnt[0][da3], 1);
            atomicAdd(&g_cnt[1][db0], 1);
            if (db1 >= 0) atomicAdd(&g_cnt[1][db1], 1);
            if (db2 >= 0) atomicAdd(&g_cnt[1][db2], 1);
            if (db3 >= 0) atomicAdd(&g_cnt[1][db3], 1);
        }
    } else {
        int i = (blockIdx.x - HB) * blockDim.x + threadIdx.x;
        const int stride = PB * 256;
        for (int idx = i; idx < NN * IND; idx += stride) {
            float v = hsrc[idx];
            __nv_bfloat16 h = __float2bfloat16_rn(v);
            g_h_hi[idx] = h;
            g_h_lo[idx] = __float2bfloat16_rn(v - __bfloat162float(h));
        }
        for (int idx = i; idx < 2 * FF * IND; idx += stride) {
            int p = idx >> 15;
            int r = idx & 32767;
            int n = r >> 7;
            int k = r & 127;
            float w = (p ? W_b : W_a)[k * FF + n];
            __nv_bfloat16 h = __float2bfloat16_rn(w);
            g_wt_hi[p][n * IND + k] = h;
            g_wt_lo[p][n * IND + k] = __float2bfloat16_rn(w - __bfloat162float(h));
        }
        for (int idx = i; idx < SEMH * FF; idx += stride) {
            int n = idx >> 8;
            int k = idx & 255;
            g_wsemt[n * FF + k] = __float2half_rn(Wsem[k * SEMH + n]);
        }
    }
}

// ---------------- K2: exclusive scan; re-zeroes cnt + qsum ------------------
__global__ void scan_kernel() {
    int p = blockIdx.x;
    int* cnt = g_cnt[p];
    int* off = g_off[p];
    int* cur = g_cur[p];
    __shared__ int sums[1024];
    int t = threadIdx.x;
    const int CH = (NN + 1023) / 1024;
    int base = t * CH;
    int local[CH];
    int s = 0;
    for (int i = 0; i < CH; i++) {
        int idx = base + i;
        int c = (idx < NN) ? cnt[idx] : 0;
        local[i] = c;
        s += c;
    }
    sums[t] = s;
    __syncthreads();
    for (int d = 1; d < 1024; d <<= 1) {
        int v = (t >= d) ? sums[t - d] : 0;
        __syncthreads();
        sums[t] += v;
        __syncthreads();
    }
    int run = (t == 0) ? 0 : sums[t - 1];
    for (int i = 0; i < CH; i++) {
        int idx = base + i;
        if (idx < NN) {
            off[idx] = run;
            cur[idx] = run;
            cnt[idx] = 0;          // reset for next graph replay
            run += local[i];
        }
    }
    if (t == 0) { off[NN] = EE; g_qsum[p] = 0.f; }
}

// ---------------- K3: feat GEMM (blockIdx.x<2) + CSR scatter (x==2) ---------
#define FPITCH_B 272          // 136 elems * 2B, conflict-free LDSM
#define FG_AHI 0
#define FG_ALO 34816
#define FG_BHI 69632
#define FG_BLO 104448
#define FG_AL  139264
#define FG_AR  140288
#define FG_SMEM 141312

__global__ __launch_bounds__(256, 1)
void gemm_scatter_kernel(const float* __restrict__ al_a, const float* __restrict__ ar_a,
                         const float* __restrict__ al_b, const float* __restrict__ ar_b,
                         const int* __restrict__ src_a, const int* __restrict__ dst_a,
                         const int* __restrict__ src_b, const int* __restrict__ dst_b) {
    if (blockIdx.x == 2) {
        // -------- CSR scatter (4-way batched) --------
        int b = blockIdx.y + NB * blockIdx.z;   // 0..2*NB-1, use first SCB
        if (b >= SCB) return;
        int t = b * blockDim.x + threadIdx.x;
        const int T = SCB * 256;
        for (int base = t; base < EE; base += 4 * T) {
            int j0 = base, j1 = base + T, j2 = base + 2 * T, j3 = base + 3 * T;
            bool v1 = j1 < EE, v2 = j2 < EE, v3 = j3 < EE;
            int da0 = dst_a[j0], sa0 = src_a[j0];
            int da1 = v1 ? dst_a[j1] : 0, sa1 = v1 ? src_a[j1] : 0;
            int da2 = v2 ? dst_a[j2] : 0, sa2 = v2 ? src_a[j2] : 0;
            int da3 = v3 ? dst_a[j3] : 0, sa3 = v3 ? src_a[j3] : 0;
            int db0 = dst_b[j0], sb0 = src_b[j0];
            int db1 = v1 ? dst_b[j1] : 0, sb1 = v1 ? src_b[j1] : 0;
            int db2 = v2 ? dst_b[j2] : 0, sb2 = v2 ? src_b[j2] : 0;
            int db3 = v3 ? dst_b[j3] : 0, sb3 = v3 ? src_b[j3] : 0;
            int pa0 = atomicAdd(&g_cur[0][da0], 1);
            int pa1 = v1 ? atomicAdd(&g_cur[0][da1], 1) : 0;
            int pa2 = v2 ? atomicAdd(&g_cur[0][da2], 1) : 0;
            int pa3 = v3 ? atomicAdd(&g_cur[0][da3], 1) : 0;
            int pb0 = atomicAdd(&g_cur[1][db0], 1);
            int pb1 = v1 ? atomicAdd(&g_cur[1][db1], 1) : 0;
            int pb2 = v2 ? atomicAdd(&g_cur[1][db2], 1) : 0;
            int pb3 = v3 ? atomicAdd(&g_cur[1][db3], 1) : 0;
            g_csrc[0][pa0] = sa0;
            if (v1) g_csrc[0][pa1] = sa1;
            if (v2) g_csrc[0][pa2] = sa2;
            if (v3) g_csrc[0][pa3] = sa3;
            g_csrc[1][pb0] = sb0;
            if (v1) g_csrc[1][pb1] = sb1;
            if (v2) g_csrc[1][pb2] = sb2;
            if (v3) g_csrc[1][pb3] = sb3;
        }
        return;
    }

    // -------- feat GEMM: B-resident, loops over 4 M-tiles --------
    extern __shared__ char smb[];
    uint32_t sb = smem_u32(smb);
    int tid = threadIdx.x;
    int wid = tid >> 5, lane = tid & 31;
    int bn = blockIdx.x * 128;
    int path = blockIdx.z;

    {
        const float* alp = path ? al_b : al_a;
        const float* arp = path ? ar_b : ar_a;
        ((float*)(smb + FG_AL))[tid] = alp[tid];
        ((float*)(smb + FG_AR))[tid] = arp[tid];
    }
    {
        int row = tid >> 1;
        int halfk = (tid & 1) * 64;
        const uint4* sh = (const uint4*)(g_wt_hi[path] + (size_t)(bn + row) * IND + halfk);
        const uint4* sl = (const uint4*)(g_wt_lo[path] + (size_t)(bn + row) * IND + halfk);
#pragma unroll
        for (int j = 0; j < 8; j++) {
            int boff = row * FPITCH_B + (halfk + j * 8) * 2;
            *(uint4*)(smb + FG_BHI + boff) = sh[j];
            *(uint4*)(smb + FG_BLO + boff) = sl[j];
        }
    }

    int wm = wid & 3, wn = wid >> 2;
    int a_row_off = (lane & 15);
    int a_k_off = (lane >> 4) << 3;
    int b_seg = lane >> 3;
    int b_n_off = (lane & 7) + ((b_seg >= 2) ? 8 : 0);
    int b_k_off = (b_seg & 1) << 3;
    int g = lane >> 2;
    int cq = (lane & 3) * 2;

    const uint32_t bases[3][2] = {
        {sb + FG_AHI, sb + FG_BHI},
        {sb + FG_AHI, sb + FG_BLO},
        {sb + FG_ALO, sb + FG_BHI}};

    for (int it = 0; it < 4; it++) {
        int mt = blockIdx.y + NB * it;
        if (mt >= MT) break;
        int bm = mt * 128;

        __syncthreads();
        {
            int row = tid >> 1;
            int halfk = (tid & 1) * 64;
            int gm = bm + row;
            bool valid = gm < NN;
            const uint4* sh = (const uint4*)(g_h_hi + (size_t)gm * IND + halfk);
            const uint4* sl = (const uint4*)(g_h_lo + (size_t)gm * IND + halfk);
            uint4 zz = make_uint4(0, 0, 0, 0);
#pragma unroll
            for (int j = 0; j < 8; j++) {
                int boff = row * FPITCH_B + (halfk + j * 8) * 2;
                *(uint4*)(smb + FG_AHI + boff) = valid ? sh[j] : zz;
                *(uint4*)(smb + FG_ALO + boff) = valid ? sl[j] : zz;
            }
        }
        __syncthreads();

        float acc[2][8][4];
#pragma unroll
        for (int t = 0; t < 2; t++)
#pragma unroll
            for (int j = 0; j < 8; j++)
#pragma unroll
                for (int q = 0; q < 4; q++) acc[t][j][q] = 0.f;

#pragma unroll
        for (int s = 0; s < 3; s++) {
            uint32_t Ab = bases[s][0], Bb = bases[s][1];
#pragma unroll
            for (int k0 = 0; k0 < 128; k0 += 16) {
                uint32_t af[2][4];
#pragma unroll
                for (int t = 0; t < 2; t++) {
                    int row = wm * 32 + t * 16 + a_row_off;
                    uint32_t addr = Ab + row * FPITCH_B + (k0 + a_k_off) * 2;
                    ldsm_x4(af[t][0], af[t][1], af[t][2], af[t][3], addr);
                }
                uint32_t bf[8][2];
#pragma unroll
                for (int j = 0; j < 8; j += 2) {
                    int n = wn * 64 + j * 8 + b_n_off;
                    uint32_t addr = Bb + n * FPITCH_B + (k0 + b_k_off) * 2;
                    ldsm_x4(bf[j][0], bf[j][1], bf[j + 1][0], bf[j + 1][1], addr);
                }
#pragma unroll
                for (int t = 0; t < 2; t++)
#pragma unroll
                    for (int j = 0; j < 8; j++) mma16816_bf(acc[t][j], af[t], bf[j]);
            }
        }

        // epilogue: feat -> fp16 gmem
        uint32_t* C = (uint32_t*)(path ? g_fh_b : g_fh_a);
#pragma unroll
        for (int t = 0; t < 2; t++) {
            int r0 = bm + wm * 32 + t * 16 + g;
            int r1 = r0 + 8;
#pragma unroll
            for (int j = 0; j < 8; j++) {
                int col = bn + wn * 64 + j * 8 + cq;
                if (r0 < NN) {
                    __half2 v = __floats2half2_rn(acc[t][j][0], acc[t][j][1]);
                    C[(size_t)r0 * (FF / 2) + (col >> 1)] = *(uint32_t*)&v;
                }
                if (r1 < NN) {
                    __half2 v = __floats2half2_rn(acc[t][j][2], acc[t][j][3]);
                    C[(size_t)r1 * (FF / 2) + (col >> 1)] = *(uint32_t*)&v;
                }
            }
        }

        // fused el/er
        {
            const float* sAL = (const float*)(smb + FG_AL);
            const float* sAR = (const float*)(smb + FG_AR);
            float pel[2][2][2], per_[2][2][2];
#pragma unroll
            for (int t = 0; t < 2; t++)
#pragma unroll
                for (int rp = 0; rp < 2; rp++)
#pragma unroll
                    for (int hh = 0; hh < 2; hh++) { pel[t][rp][hh] = 0.f; per_[t][rp][hh] = 0.f; }
#pragma unroll
            for (int t = 0; t < 2; t++)
#pragma unroll
                for (int j = 0; j < 8; j++) {
                    int hh = j >> 2;
                    int col = bn + wn * 64 + j * 8 + cq;
                    float a0 = sAL[col], a1 = sAL[col + 1];
                    float b0 = sAR[col], b1 = sAR[col + 1];
                    pel[t][0][hh] += acc[t][j][0] * a0 + acc[t][j][1] * a1;
                    pel[t][1][hh] += acc[t][j][2] * a0 + acc[t][j][3] * a1;
                    per_[t][0][hh] += acc[t][j][0] * b0 + acc[t][j][1] * b1;
                    per_[t][1][hh] += acc[t][j][2] * b0 + acc[t][j][3] * b1;
                }
#pragma unroll
            for (int t = 0; t < 2; t++)
#pragma unroll
                for (int rp = 0; rp < 2; rp++)
#pragma unroll
                    for (int hh = 0; hh < 2; hh++) {
                        float v = pel[t][rp][hh];
                        v += __shfl_xor_sync(0xffffffffu, v, 1);
                        v += __shfl_xor_sync(0xffffffffu, v, 2);
                        pel[t][rp][hh] = v;
                        float u = per_[t][rp][hh];
                        u += __shfl_xor_sync(0xffffffffu, u, 1);
                        u += __shfl_xor_sync(0xffffffffu, u, 2);
                        per_[t][rp][hh] = u;
                    }
            if ((lane & 3) == 0) {
                float* eld = path ? g_el_b : g_el_a;
                float* erd = path ? g_er_b : g_er_a;
                int hb = (bn + wn * 64) >> 5;
#pragma unroll
                for (int t = 0; t < 2; t++)
#pragma unroll
                    for (int rp = 0; rp < 2; rp++) {
                        int r = bm + wm * 32 + t * 16 + g + rp * 8;
                        if (r < NN) {
                            eld[r * NHEAD + hb] = pel[t][rp][0];
                            eld[r * NHEAD + hb + 1] = pel[t][rp][1];
                            erd[r * NHEAD + hb] = per_[t][rp][0];
                            erd[r * NHEAD + hb + 1] = per_[t][rp][1];
                        }
                    }
            }
        }
    }
}

// ---------------- K4: edge softmax + aggregation (fp16, f32x2 FMA) ----------
__global__ void agg_kernel(const float* __restrict__ bias_a,
                           const float* __restrict__ bias_b) {
    int p = blockIdx.y;
    int node = (blockIdx.x * blockDim.x + threadIdx.x) >> 5;
    int lane = threadIdx.x & 31;
    if (node >= NN) return;
    const uint4* fb = (const uint4*)(p ? g_fh_b : g_fh_a);
    const float* el   = p ? g_el_b   : g_el_a;
    const float* er   = p ? g_er_b   : g_er_a;
    const float* bias = p ? bias_b   : bias_a;
    const int* csrc = g_csrc[p];
    int s0 = g_off[p][node];
    int s1 = g_off[p][node + 1];
    int hd = lane >> 2;
    float er8 = (lane < NHEAD) ? er[node * NHEAD + lane] : 0.f;

    uint64_t acc2[4];
#pragma unroll
    for (int q = 0; q < 4; q++) acc2[q] = dup_f32x2(0.f);
    float den = 0.f;

    int i = s0;
    for (; i + 4 <= s1; i += 4) {
        int sA = csrc[i], sB = csrc[i + 1], sC = csrc[i + 2], sD = csrc[i + 3];
        uint4 vA = fb[(size_t)sA * 32 + lane];
        uint4 vB = fb[(size_t)sB * 32 + lane];
        uint4 vC = fb[(size_t)sC * 32 + lane];
        uint4 vD = fb[(size_t)sD * 32 + lane];
        float wA = 0.f, wB = 0.f, wC = 0.f, wD = 0.f;
        if (lane < NHEAD) {
            float eA = el[sA * NHEAD + lane] + er8;
            float eB = el[sB * NHEAD + lane] + er8;
            float eC = el[sC * NHEAD + lane] + er8;
            float eD = el[sD * NHEAD + lane] + er8;
            eA = eA > 0.f ? eA : 0.2f * eA;
            eB = eB > 0.f ? eB : 0.2f * eB;
            eC = eC > 0.f ? eC : 0.2f * eC;
            eD = eD > 0.f ? eD : 0.2f * eD;
            wA = __expf(eA); wB = __expf(eB); wC = __expf(eC); wD = __expf(eD);
        }
        float whA = __shfl_sync(0xffffffffu, wA, hd);
        float whB = __shfl_sync(0xffffffffu, wB, hd);
        float whC = __shfl_sync(0xffffffffu, wC, hd);
        float whD = __shfl_sync(0xffffffffu, wD, hd);
        den += (whA + whB) + (whC + whD);
        fma8x2(acc2, dup_f32x2(whA), vA);
        fma8x2(acc2, dup_f32x2(whB), vB);
        fma8x2(acc2, dup_f32x2(whC), vC);
        fma8x2(acc2, dup_f32x2(whD), vD);
    }
    for (; i < s1; i++) {
        int s = csrc[i];
        uint4 v = fb[(size_t)s * 32 + lane];
        float w = 0.f;
        if (lane < NHEAD) {
            float e = el[s * NHEAD + lane] + er8;
            e = e > 0.f ? e : 0.2f * e;
            w = __expf(e);
        }
        float wh = __shfl_sync(0xffffffffu, w, hd);
        den += wh;
        fma8x2(acc2, dup_f32x2(wh), v);
    }

    float acc[8];
#pragma unroll
    for (int q = 0; q < 4; q++) {
        float lo, hi;
        asm("mov.b64 {%0,%1}, %2;" : "=f"(lo), "=f"(hi) : "l"(acc2[q]));
        acc[2 * q] = lo;
        acc[2 * q + 1] = hi;
    }

    float inv = den > 0.f ? 1.f / den : 0.f;
    float4 b0 = *(const float4*)(bias + 8 * lane);
    float4 b1 = *(const float4*)(bias + 8 * lane + 4);
    float o[8];
    o[0] = acc[0] * inv + b0.x; o[1] = acc[1] * inv + b0.y;
    o[2] = acc[2] * inv + b0.z; o[3] = acc[3] * inv + b0.w;
    o[4] = acc[4] * inv + b1.x; o[5] = acc[5] * inv + b1.y;
    o[6] = acc[6] * inv + b1.z; o[7] = acc[7] * inv + b1.w;
#pragma unroll
    for (int q = 0; q < 8; q++) o[q] = o[q] > 0.f ? o[q] : expm1f(o[q]);
    __half2 h0 = __floats2half2_rn(o[0], o[1]);
    __half2 h1 = __floats2half2_rn(o[2], o[3]);
    __half2 h2 = __floats2half2_rn(o[4], o[5]);
    __half2 h3 = __floats2half2_rn(o[6], o[7]);
    uint4 pk = make_uint4(*(uint32_t*)&h0, *(uint32_t*)&h1,
                          *(uint32_t*)&h2, *(uint32_t*)&h3);
    uint4* z = (uint4*)((p ? g_zh_b : g_zh_a) + (size_t)node * FF + 8 * lane);
    *z = pk;
}

// ---------------- K5: sem GEMM (f16 mma, K-chunked, occ>=2) -----------------
#define SPITCH 272
#define SG_A 0
#define SG_B 34816
#define SG_W 69632
#define SG_SMEM 70656

__global__ __launch_bounds__(256)
void sem_gemm_mma(const float* __restrict__ bsem, const float* __restrict__ wsem) {
    extern __shared__ char smb[];
    uint32_t sb = smem_u32(smb);
    int tid = threadIdx.x;
    int wid = tid >> 5, lane = tid & 31;
    int bm = blockIdx.x * 128;
    int path = blockIdx.y;
    const __half* A = path ? g_zh_b : g_zh_a;

    if (tid < SEMH) {
        ((float*)(smb + SG_W))[tid] = bsem[tid];
        ((float*)(smb + SG_W))[SEMH + tid] = wsem[tid];
    }

    int wm = wid & 3, wn = wid >> 2;
    float acc[2][8][4];
#pragma unroll
    for (int t = 0; t < 2; t++)
#pragma unroll
        for (int j = 0; j < 8; j++)
#pragma unroll
            for (int q = 0; q < 4; q++) acc[t][j][q] = 0.f;

    int a_row_off = (lane & 15);
    int a_k_off = (lane >> 4) << 3;
    int b_seg = lane >> 3;
    int b_n_off = (lane & 7) + ((b_seg >= 2) ? 8 : 0);
    int b_k_off = (b_seg & 1) << 3;

    for (int kc = 0; kc < 2; kc++) {
        if (kc) __syncthreads();   // prior chunk's LDSM reads complete
        {
            int row = tid >> 1;
            int half = (tid & 1) * 64;   // elems within chunk
            int gm = bm + row;
            bool valid = gm < NN;
            const uint4* src = (const uint4*)(A + (size_t)gm * FF + kc * 128 + half);
            uint4 zz = make_uint4(0, 0, 0, 0);
#pragma unroll
            for (int j = 0; j < 8; j++) {
                *(uint4*)(smb + SG_A + row * SPITCH + (half + j * 8) * 2) =
                    valid ? src[j] : zz;
            }
        }
        {
            int row = tid >> 1;
            int halfk = (tid & 1) * 64;
            const uint4* sh = (const uint4*)(g_wsemt + row * FF + kc * 128 + halfk);
#pragma unroll
            for (int j = 0; j < 8; j++) {
                *(uint4*)(smb + SG_B + row * SPITCH + (halfk + j * 8) * 2) = sh[j];
            }
        }
        __syncthreads();

#pragma unroll
        for (int k0 = 0; k0 < 128; k0 += 16) {
            uint32_t af[2][4];
#pragma unroll
            for (int t = 0; t < 2; t++) {
                int row = wm * 32 + t * 16 + a_row_off;
                uint32_t addr = sb + SG_A + row * SPITCH + (k0 + a_k_off) * 2;
                ldsm_x4(af[t][0], af[t][1], af[t][2], af[t][3], addr);
            }
            uint32_t bf[8][2];
#pragma unroll
            for (int j = 0; j < 8; j += 2) {
                int n = wn * 64 + j * 8 + b_n_off;
                uint32_t addr = sb + SG_B + n * SPITCH + (k0 + b_k_off) * 2;
                ldsm_x4(bf[j][0], bf[j][1], bf[j + 1][0], bf[j + 1][1], addr);
            }
#pragma unroll
            for (int t = 0; t < 2; t++)
#pragma unroll
                for (int j = 0; j < 8; j++) mma16816_f16(acc[t][j], af[t], bf[j]);
        }
    }

    const float* sbm = (const float*)(smb + SG_W);
    const float* swm = sbm + SEMH;
    int g = lane >> 2;
    int cq = (lane & 3) * 2;
    float part = 0.f;
#pragma unroll
    for (int t = 0; t < 2; t++) {
        int r0 = bm + wm * 32 + t * 16 + g;
        int r1 = r0 + 8;
#pragma unroll
        for (int j = 0; j < 8; j++) {
            int col = wn * 64 + j * 8 + cq;
            float b0 = sbm[col], b1 = sbm[col + 1];
            float w0 = swm[col], w1 = swm[col + 1];
            if (r0 < NN)
                part += tanh_fast(acc[t][j][0] + b0) * w0 +
                        tanh_fast(acc[t][j][1] + b1) * w1;
            if (r1 < NN)
                part += tanh_fast(acc[t][j][2] + b0) * w0 +
                        tanh_fast(acc[t][j][3] + b1) * w1;
        }
    }
#pragma unroll
    for (int o = 16; o > 0; o >>= 1) part += __shfl_xor_sync(0xffffffffu, part, o);
    __shared__ float warp_part[8];
    if (lane == 0) warp_part[wid] = part;
    __syncthreads();
    if (tid == 0) {
        float s = 0.f;
#pragma unroll
        for (int w = 0; w < 8; w++) s += warp_part[w];
        atomicAdd(&g_qsum[path], s);
    }
}

// ---------------- K6: final combine (beta fused, fp16 z inputs) -------------
__global__ void combine_kernel(float* __restrict__ out) {
    float qa = g_qsum[0] * (1.f / (float)NN);
    float qb = g_qsum[1] * (1.f / (float)NN);
    float m = fmaxf(qa, qb);
    float ea = __expf(qa - m), eb = __expf(qb - m);
    float inv = 1.f / (ea + eb);
    float b0 = ea * inv, b1 = eb * inv;
    int i0 = blockIdx.x * blockDim.x + threadIdx.x;
    int stride = gridDim.x * blockDim.x;
    const uint2* za = (const uint2*)g_zh_a;   // 4 halfs each
    const uint2* zb = (const uint2*)g_zh_b;
    float4* o = (float4*)out;
    for (int i = i0; i < NN * FF / 4; i += stride) {
        uint2 a = za[i];
        uint2 b = zb[i];
        float2 a0 = __half22float2(*(__half2*)&a.x);
        float2 a1 = __half22float2(*(__half2*)&a.y);
        float2 c0 = __half22float2(*(__half2*)&b.x);
        float2 c1 = __half22float2(*(__half2*)&b.y);
        float4 r;
        r.x = b0 * a0.x + b1 * c0.x;
        r.y = b0 * a0.y + b1 * c0.y;
        r.z = b0 * a1.x + b1 * c1.x;
        r.w = b0 * a1.y + b1 * c1.y;
        o[i] = r;
    }
}

// ---------------- launch ----------------------------------------------------
extern "C" void kernel_launch(void* const* d_in, const int* in_sizes, int n_in,
                              void* d_out, int out_size) {
    const float* h     = (const float*)d_in[0];
    const int* src_a   = (const int*)d_in[1];
    const int* dst_a   = (const int*)d_in[2];
    const int* src_b   = (const int*)d_in[3];
    const int* dst_b   = (const int*)d_in[4];
    const float* W_a   = (const float*)d_in[5];
    const float* al_a  = (const float*)d_in[6];
    const float* ar_a  = (const float*)d_in[7];
    const float* bias_a= (const float*)d_in[8];
    const float* W_b   = (const float*)d_in[9];
    const float* al_b  = (const float*)d_in[10];
    const float* ar_b  = (const float*)d_in[11];
    const float* bias_b= (const float*)d_in[12];
    const float* Wsem  = (const float*)d_in[13];
    const float* bsem  = (const float*)d_in[14];
    const float* wsem  = (const float*)d_in[15];
    float* out = (float*)d_out;

    cudaFuncSetAttribute(gemm_scatter_kernel, cudaFuncAttributeMaxDynamicSharedMemorySize, FG_SMEM);
    cudaFuncSetAttribute(sem_gemm_mma, cudaFuncAttributeMaxDynamicSharedMemorySize, SG_SMEM);

    hist_prep_kernel<<<HB + PB, 256>>>(dst_a, dst_b, h, W_a, W_b, Wsem);
    scan_kernel<<<2, 1024>>>();

    dim3 ggs(3, NB, 2);
    gemm_scatter_kernel<<<ggs, 256, FG_SMEM>>>(al_a, ar_a, al_b, ar_b,
                                               src_a, dst_a, src_b, dst_b);

    dim3 gagg((NN + 7) / 8, 2);
    agg_kernel<<<gagg, 256>>>(bias_a, bias_b);

    dim3 gsem(MT, 2);
    sem_gemm_mma<<<gsem, 256, SG_SMEM>>>(bsem, wsem);

    combine_kernel<<<2048, 256>>>(out);
}

// round 14
// speedup vs baseline: 1.0309x; 1.0309x over previous
#include <cuda_runtime.h>
#include <cuda_bf16.h>
#include <cuda_fp16.h>
#include <math.h>
#include <stdint.h>

#define NN    50000
#define IND   128
#define OUTD  32
#define NHEAD 8
#define EE    800000
#define FF    256      // OUTD*NHEAD
#define SEMH  128
#define MT    ((NN + 127) / 128)   // 391 M-tiles
#define NB    98                   // M-chunks per ntile/path CTA column
#define HB    196                  // hist blocks inside hist_prep
#define PB    512                  // prep blocks inside hist_prep
#define SCB   196                  // scatter chunk-blocks inside gemm launch

// ---------------- scratch (device globals: allocation-free rule) ------------
__device__ __half g_fh_a[NN * FF];     // feat fp16 (gather payload)
__device__ __half g_fh_b[NN * FF];
__device__ __half g_zh_a[NN * FF];     // z fp16
__device__ __half g_zh_b[NN * FF];
__device__ float g_el_a[NN * NHEAD];
__device__ float g_er_a[NN * NHEAD];
__device__ float g_el_b[NN * NHEAD];
__device__ float g_er_b[NN * NHEAD];
__device__ int   g_cnt[2][NN];         // zero at load; scan re-zeroes each run
__device__ int   g_off[2][NN + 1];
__device__ int   g_cur[2][NN];
__device__ int   g_csrc[2][EE];
__device__ float g_qsum[2];
// pre-split inputs
__device__ __nv_bfloat16 g_h_hi[NN * IND];
__device__ __nv_bfloat16 g_h_lo[NN * IND];
__device__ __nv_bfloat16 g_wt_hi[2][FF * IND];
__device__ __nv_bfloat16 g_wt_lo[2][FF * IND];
__device__ __half g_wsemt[SEMH * FF];  // fp16 Wsem^T

// ==================== helpers ===============================================
__device__ __forceinline__ uint32_t smem_u32(const void* p) {
    uint32_t a;
    asm("{ .reg .u64 t; cvta.to.shared.u64 t, %1; cvt.u32.u64 %0, t; }"
        : "=r"(a) : "l"(p));
    return a;
}
__device__ __forceinline__ void ldsm_x4(uint32_t& r0, uint32_t& r1,
                                        uint32_t& r2, uint32_t& r3, uint32_t addr) {
    asm volatile("ldmatrix.sync.aligned.m8n8.x4.shared.b16 {%0,%1,%2,%3}, [%4];"
                 : "=r"(r0), "=r"(r1), "=r"(r2), "=r"(r3) : "r"(addr));
}
__device__ __forceinline__ void mma16816_bf(float* d, const uint32_t* a, const uint32_t* b) {
    asm volatile(
        "mma.sync.aligned.m16n8k16.row.col.f32.bf16.bf16.f32 "
        "{%0,%1,%2,%3}, {%4,%5,%6,%7}, {%8,%9}, {%0,%1,%2,%3};"
        : "+f"(d[0]), "+f"(d[1]), "+f"(d[2]), "+f"(d[3])
        : "r"(a[0]), "r"(a[1]), "r"(a[2]), "r"(a[3]), "r"(b[0]), "r"(b[1]));
}
__device__ __forceinline__ void mma16816_f16(float* d, const uint32_t* a, const uint32_t* b) {
    asm volatile(
        "mma.sync.aligned.m16n8k16.row.col.f32.f16.f16.f32 "
        "{%0,%1,%2,%3}, {%4,%5,%6,%7}, {%8,%9}, {%0,%1,%2,%3};"
        : "+f"(d[0]), "+f"(d[1]), "+f"(d[2]), "+f"(d[3])
        : "r"(a[0]), "r"(a[1]), "r"(a[2]), "r"(a[3]), "r"(b[0]), "r"(b[1]));
}
__device__ __forceinline__ float tanh_fast(float x) {
    float y; asm("tanh.approx.f32 %0, %1;" : "=f"(y) : "f"(x)); return y;
}
// fp32 scalar accumulate of 8 dims (remainder path)
__device__ __forceinline__ void fma8(float* acc, float w, const uint4& v) {
    float2 f0 = __half22float2(*(__half2*)&v.x);
    float2 f1 = __half22float2(*(__half2*)&v.y);
    float2 f2 = __half22float2(*(__half2*)&v.z);
    float2 f3 = __half22float2(*(__half2*)&v.w);
    acc[0] = fmaf(w, f0.x, acc[0]); acc[1] = fmaf(w, f0.y, acc[1]);
    acc[2] = fmaf(w, f1.x, acc[2]); acc[3] = fmaf(w, f1.y, acc[3]);
    acc[4] = fmaf(w, f2.x, acc[4]); acc[5] = fmaf(w, f2.y, acc[5]);
    acc[6] = fmaf(w, f3.x, acc[6]); acc[7] = fmaf(w, f3.y, acc[7]);
}
// fp16 packed accumulate of 8 dims (4 HFMA2)
__device__ __forceinline__ void hfma8(__half2* hacc, __half2 w2, const uint4& v) {
    hacc[0] = __hfma2(w2, *(__half2*)&v.x, hacc[0]);
    hacc[1] = __hfma2(w2, *(__half2*)&v.y, hacc[1]);
    hacc[2] = __hfma2(w2, *(__half2*)&v.z, hacc[2]);
    hacc[3] = __hfma2(w2, *(__half2*)&v.w, hacc[3]);
}

// ---------------- K1: hist (blocks 0..HB-1) + prep (blocks HB..HB+PB-1) -----
__global__ void hist_prep_kernel(const int* __restrict__ dst_a,
                                 const int* __restrict__ dst_b,
                                 const float* __restrict__ hsrc,
                                 const float* __restrict__ W_a,
                                 const float* __restrict__ W_b,
                                 const float* __restrict__ Wsem) {
    if (blockIdx.x < HB) {
        int t = blockIdx.x * blockDim.x + threadIdx.x;
        const int T = HB * 256;
        for (int base = t; base < EE; base += 4 * T) {
            int j0 = base, j1 = base + T, j2 = base + 2 * T, j3 = base + 3 * T;
            int da0 = dst_a[j0];
            int da1 = j1 < EE ? dst_a[j1] : -1;
            int da2 = j2 < EE ? dst_a[j2] : -1;
            int da3 = j3 < EE ? dst_a[j3] : -1;
            int db0 = dst_b[j0];
            int db1 = j1 < EE ? dst_b[j1] : -1;
            int db2 = j2 < EE ? dst_b[j2] : -1;
            int db3 = j3 < EE ? dst_b[j3] : -1;
            atomicAdd(&g_cnt[0][da0], 1);
            if (da1 >= 0) atomicAdd(&g_cnt[0][da1], 1);
            if (da2 >= 0) atomicAdd(&g_cnt[0][da2], 1);
            if (da3 >= 0) atomicAdd(&g_cnt[0][da3], 1);
            atomicAdd(&g_cnt[1][db0], 1);
            if (db1 >= 0) atomicAdd(&g_cnt[1][db1], 1);
            if (db2 >= 0) atomicAdd(&g_cnt[1][db2], 1);
            if (db3 >= 0) atomicAdd(&g_cnt[1][db3], 1);
        }
    } else {
        int i = (blockIdx.x - HB) * blockDim.x + threadIdx.x;
        const int stride = PB * 256;
        for (int idx = i; idx < NN * IND; idx += stride) {
            float v = hsrc[idx];
            __nv_bfloat16 h = __float2bfloat16_rn(v);
            g_h_hi[idx] = h;
            g_h_lo[idx] = __float2bfloat16_rn(v - __bfloat162float(h));
        }
        for (int idx = i; idx < 2 * FF * IND; idx += stride) {
            int p = idx >> 15;
            int r = idx & 32767;
            int n = r >> 7;
            int k = r & 127;
            float w = (p ? W_b : W_a)[k * FF + n];
            __nv_bfloat16 h = __float2bfloat16_rn(w);
            g_wt_hi[p][n * IND + k] = h;
            g_wt_lo[p][n * IND + k] = __float2bfloat16_rn(w - __bfloat162float(h));
        }
        for (int idx = i; idx < SEMH * FF; idx += stride) {
            int n = idx >> 8;
            int k = idx & 255;
            g_wsemt[n * FF + k] = __float2half_rn(Wsem[k * SEMH + n]);
        }
    }
}

// ---------------- K2: exclusive scan; re-zeroes cnt + qsum ------------------
__global__ void scan_kernel() {
    int p = blockIdx.x;
    int* cnt = g_cnt[p];
    int* off = g_off[p];
    int* cur = g_cur[p];
    __shared__ int sums[1024];
    int t = threadIdx.x;
    const int CH = (NN + 1023) / 1024;
    int base = t * CH;
    int local[CH];
    int s = 0;
    for (int i = 0; i < CH; i++) {
        int idx = base + i;
        int c = (idx < NN) ? cnt[idx] : 0;
        local[i] = c;
        s += c;
    }
    sums[t] = s;
    __syncthreads();
    for (int d = 1; d < 1024; d <<= 1) {
        int v = (t >= d) ? sums[t - d] : 0;
        __syncthreads();
        sums[t] += v;
        __syncthreads();
    }
    int run = (t == 0) ? 0 : sums[t - 1];
    for (int i = 0; i < CH; i++) {
        int idx = base + i;
        if (idx < NN) {
            off[idx] = run;
            cur[idx] = run;
            cnt[idx] = 0;          // reset for next graph replay
            run += local[i];
        }
    }
    if (t == 0) { off[NN] = EE; g_qsum[p] = 0.f; }
}

// ---------------- K3: feat GEMM (blockIdx.x<2) + CSR scatter (x==2) ---------
#define FPITCH_B 272          // 136 elems * 2B, conflict-free LDSM
#define FG_AHI 0
#define FG_ALO 34816
#define FG_BHI 69632
#define FG_BLO 104448
#define FG_AL  139264
#define FG_AR  140288
#define FG_SMEM 141312

__global__ __launch_bounds__(256, 1)
void gemm_scatter_kernel(const float* __restrict__ al_a, const float* __restrict__ ar_a,
                         const float* __restrict__ al_b, const float* __restrict__ ar_b,
                         const int* __restrict__ src_a, const int* __restrict__ dst_a,
                         const int* __restrict__ src_b, const int* __restrict__ dst_b) {
    if (blockIdx.x == 2) {
        // -------- CSR scatter (4-way batched) --------
        int b = blockIdx.y + NB * blockIdx.z;   // 0..2*NB-1, use first SCB
        if (b >= SCB) return;
        int t = b * blockDim.x + threadIdx.x;
        const int T = SCB * 256;
        for (int base = t; base < EE; base += 4 * T) {
            int j0 = base, j1 = base + T, j2 = base + 2 * T, j3 = base + 3 * T;
            bool v1 = j1 < EE, v2 = j2 < EE, v3 = j3 < EE;
            int da0 = dst_a[j0], sa0 = src_a[j0];
            int da1 = v1 ? dst_a[j1] : 0, sa1 = v1 ? src_a[j1] : 0;
            int da2 = v2 ? dst_a[j2] : 0, sa2 = v2 ? src_a[j2] : 0;
            int da3 = v3 ? dst_a[j3] : 0, sa3 = v3 ? src_a[j3] : 0;
            int db0 = dst_b[j0], sb0 = src_b[j0];
            int db1 = v1 ? dst_b[j1] : 0, sb1 = v1 ? src_b[j1] : 0;
            int db2 = v2 ? dst_b[j2] : 0, sb2 = v2 ? src_b[j2] : 0;
            int db3 = v3 ? dst_b[j3] : 0, sb3 = v3 ? src_b[j3] : 0;
            int pa0 = atomicAdd(&g_cur[0][da0], 1);
            int pa1 = v1 ? atomicAdd(&g_cur[0][da1], 1) : 0;
            int pa2 = v2 ? atomicAdd(&g_cur[0][da2], 1) : 0;
            int pa3 = v3 ? atomicAdd(&g_cur[0][da3], 1) : 0;
            int pb0 = atomicAdd(&g_cur[1][db0], 1);
            int pb1 = v1 ? atomicAdd(&g_cur[1][db1], 1) : 0;
            int pb2 = v2 ? atomicAdd(&g_cur[1][db2], 1) : 0;
            int pb3 = v3 ? atomicAdd(&g_cur[1][db3], 1) : 0;
            g_csrc[0][pa0] = sa0;
            if (v1) g_csrc[0][pa1] = sa1;
            if (v2) g_csrc[0][pa2] = sa2;
            if (v3) g_csrc[0][pa3] = sa3;
            g_csrc[1][pb0] = sb0;
            if (v1) g_csrc[1][pb1] = sb1;
            if (v2) g_csrc[1][pb2] = sb2;
            if (v3) g_csrc[1][pb3] = sb3;
        }
        return;
    }

    // -------- feat GEMM: B-resident, loops over 4 M-tiles --------
    extern __shared__ char smb[];
    uint32_t sb = smem_u32(smb);
    int tid = threadIdx.x;
    int wid = tid >> 5, lane = tid & 31;
    int bn = blockIdx.x * 128;
    int path = blockIdx.z;

    {
        const float* alp = path ? al_b : al_a;
        const float* arp = path ? ar_b : ar_a;
        ((float*)(smb + FG_AL))[tid] = alp[tid];
        ((float*)(smb + FG_AR))[tid] = arp[tid];
    }
    {
        int row = tid >> 1;
        int halfk = (tid & 1) * 64;
        const uint4* sh = (const uint4*)(g_wt_hi[path] + (size_t)(bn + row) * IND + halfk);
        const uint4* sl = (const uint4*)(g_wt_lo[path] + (size_t)(bn + row) * IND + halfk);
#pragma unroll
        for (int j = 0; j < 8; j++) {
            int boff = row * FPITCH_B + (halfk + j * 8) * 2;
            *(uint4*)(smb + FG_BHI + boff) = sh[j];
            *(uint4*)(smb + FG_BLO + boff) = sl[j];
        }
    }

    int wm = wid & 3, wn = wid >> 2;
    int a_row_off = (lane & 15);
    int a_k_off = (lane >> 4) << 3;
    int b_seg = lane >> 3;
    int b_n_off = (lane & 7) + ((b_seg >= 2) ? 8 : 0);
    int b_k_off = (b_seg & 1) << 3;
    int g = lane >> 2;
    int cq = (lane & 3) * 2;

    const uint32_t bases[3][2] = {
        {sb + FG_AHI, sb + FG_BHI},
        {sb + FG_AHI, sb + FG_BLO},
        {sb + FG_ALO, sb + FG_BHI}};

    for (int it = 0; it < 4; it++) {
        int mt = blockIdx.y + NB * it;
        if (mt >= MT) break;
        int bm = mt * 128;

        __syncthreads();
        {
            int row = tid >> 1;
            int halfk = (tid & 1) * 64;
            int gm = bm + row;
            bool valid = gm < NN;
            const uint4* sh = (const uint4*)(g_h_hi + (size_t)gm * IND + halfk);
            const uint4* sl = (const uint4*)(g_h_lo + (size_t)gm * IND + halfk);
            uint4 zz = make_uint4(0, 0, 0, 0);
#pragma unroll
            for (int j = 0; j < 8; j++) {
                int boff = row * FPITCH_B + (halfk + j * 8) * 2;
                *(uint4*)(smb + FG_AHI + boff) = valid ? sh[j] : zz;
                *(uint4*)(smb + FG_ALO + boff) = valid ? sl[j] : zz;
            }
        }
        __syncthreads();

        float acc[2][8][4];
#pragma unroll
        for (int t = 0; t < 2; t++)
#pragma unroll
            for (int j = 0; j < 8; j++)
#pragma unroll
                for (int q = 0; q < 4; q++) acc[t][j][q] = 0.f;

#pragma unroll
        for (int s = 0; s < 3; s++) {
            uint32_t Ab = bases[s][0], Bb = bases[s][1];
#pragma unroll
            for (int k0 = 0; k0 < 128; k0 += 16) {
                uint32_t af[2][4];
#pragma unroll
                for (int t = 0; t < 2; t++) {
                    int row = wm * 32 + t * 16 + a_row_off;
                    uint32_t addr = Ab + row * FPITCH_B + (k0 + a_k_off) * 2;
                    ldsm_x4(af[t][0], af[t][1], af[t][2], af[t][3], addr);
                }
                uint32_t bf[8][2];
#pragma unroll
                for (int j = 0; j < 8; j += 2) {
                    int n = wn * 64 + j * 8 + b_n_off;
                    uint32_t addr = Bb + n * FPITCH_B + (k0 + b_k_off) * 2;
                    ldsm_x4(bf[j][0], bf[j][1], bf[j + 1][0], bf[j + 1][1], addr);
                }
#pragma unroll
                for (int t = 0; t < 2; t++)
#pragma unroll
                    for (int j = 0; j < 8; j++) mma16816_bf(acc[t][j], af[t], bf[j]);
            }
        }

        // epilogue: feat -> fp16 gmem
        uint32_t* C = (uint32_t*)(path ? g_fh_b : g_fh_a);
#pragma unroll
        for (int t = 0; t < 2; t++) {
            int r0 = bm + wm * 32 + t * 16 + g;
            int r1 = r0 + 8;
#pragma unroll
            for (int j = 0; j < 8; j++) {
                int col = bn + wn * 64 + j * 8 + cq;
                if (r0 < NN) {
                    __half2 v = __floats2half2_rn(acc[t][j][0], acc[t][j][1]);
                    C[(size_t)r0 * (FF / 2) + (col >> 1)] = *(uint32_t*)&v;
                }
                if (r1 < NN) {
                    __half2 v = __floats2half2_rn(acc[t][j][2], acc[t][j][3]);
                    C[(size_t)r1 * (FF / 2) + (col >> 1)] = *(uint32_t*)&v;
                }
            }
        }

        // fused el/er
        {
            const float* sAL = (const float*)(smb + FG_AL);
            const float* sAR = (const float*)(smb + FG_AR);
            float pel[2][2][2], per_[2][2][2];
#pragma unroll
            for (int t = 0; t < 2; t++)
#pragma unroll
                for (int rp = 0; rp < 2; rp++)
#pragma unroll
                    for (int hh = 0; hh < 2; hh++) { pel[t][rp][hh] = 0.f; per_[t][rp][hh] = 0.f; }
#pragma unroll
            for (int t = 0; t < 2; t++)
#pragma unroll
                for (int j = 0; j < 8; j++) {
                    int hh = j >> 2;
                    int col = bn + wn * 64 + j * 8 + cq;
                    float a0 = sAL[col], a1 = sAL[col + 1];
                    float b0 = sAR[col], b1 = sAR[col + 1];
                    pel[t][0][hh] += acc[t][j][0] * a0 + acc[t][j][1] * a1;
                    pel[t][1][hh] += acc[t][j][2] * a0 + acc[t][j][3] * a1;
                    per_[t][0][hh] += acc[t][j][0] * b0 + acc[t][j][1] * b1;
                    per_[t][1][hh] += acc[t][j][2] * b0 + acc[t][j][3] * b1;
                }
#pragma unroll
            for (int t = 0; t < 2; t++)
#pragma unroll
                for (int rp = 0; rp < 2; rp++)
#pragma unroll
                    for (int hh = 0; hh < 2; hh++) {
                        float v = pel[t][rp][hh];
                        v += __shfl_xor_sync(0xffffffffu, v, 1);
                        v += __shfl_xor_sync(0xffffffffu, v, 2);
                        pel[t][rp][hh] = v;
                        float u = per_[t][rp][hh];
                        u += __shfl_xor_sync(0xffffffffu, u, 1);
                        u += __shfl_xor_sync(0xffffffffu, u, 2);
                        per_[t][rp][hh] = u;
                    }
            if ((lane & 3) == 0) {
                float* eld = path ? g_el_b : g_el_a;
                float* erd = path ? g_er_b : g_er_a;
                int hb = (bn + wn * 64) >> 5;
#pragma unroll
                for (int t = 0; t < 2; t++)
#pragma unroll
                    for (int rp = 0; rp < 2; rp++) {
                        int r = bm + wm * 32 + t * 16 + g + rp * 8;
                        if (r < NN) {
                            eld[r * NHEAD + hb] = pel[t][rp][0];
                            eld[r * NHEAD + hb + 1] = pel[t][rp][1];
                            erd[r * NHEAD + hb] = per_[t][rp][0];
                            erd[r * NHEAD + hb + 1] = per_[t][rp][1];
                        }
                    }
            }
        }
    }
}

// ---------------- K4: edge softmax + aggregation (fp16 HFMA2, flush x4) -----
__global__ void agg_kernel(const float* __restrict__ bias_a,
                           const float* __restrict__ bias_b) {
    int p = blockIdx.y;
    int node = (blockIdx.x * blockDim.x + threadIdx.x) >> 5;
    int lane = threadIdx.x & 31;
    if (node >= NN) return;
    const uint4* fb = (const uint4*)(p ? g_fh_b : g_fh_a);
    const float* el   = p ? g_el_b   : g_el_a;
    const float* er   = p ? g_er_b   : g_er_a;
    const float* bias = p ? bias_b   : bias_a;
    const int* csrc = g_csrc[p];
    int s0 = g_off[p][node];
    int s1 = g_off[p][node + 1];
    int hd = lane >> 2;
    float er8 = (lane < NHEAD) ? er[node * NHEAD + lane] : 0.f;

    float acc[8];
#pragma unroll
    for (int q = 0; q < 8; q++) acc[q] = 0.f;
    float den = 0.f;

    int i = s0;
    for (; i + 4 <= s1; i += 4) {
        int sA = csrc[i], sB = csrc[i + 1], sC = csrc[i + 2], sD = csrc[i + 3];
        uint4 vA = fb[(size_t)sA * 32 + lane];
        uint4 vB = fb[(size_t)sB * 32 + lane];
        uint4 vC = fb[(size_t)sC * 32 + lane];
        uint4 vD = fb[(size_t)sD * 32 + lane];
        float wA = 0.f, wB = 0.f, wC = 0.f, wD = 0.f;
        if (lane < NHEAD) {
            float eA = el[sA * NHEAD + lane] + er8;
            float eB = el[sB * NHEAD + lane] + er8;
            float eC = el[sC * NHEAD + lane] + er8;
            float eD = el[sD * NHEAD + lane] + er8;
            eA = eA > 0.f ? eA : 0.2f * eA;
            eB = eB > 0.f ? eB : 0.2f * eB;
            eC = eC > 0.f ? eC : 0.2f * eC;
            eD = eD > 0.f ? eD : 0.2f * eD;
            wA = __expf(eA); wB = __expf(eB); wC = __expf(eC); wD = __expf(eD);
        }
        float whA = __shfl_sync(0xffffffffu, wA, hd);
        float whB = __shfl_sync(0xffffffffu, wB, hd);
        float whC = __shfl_sync(0xffffffffu, wC, hd);
        float whD = __shfl_sync(0xffffffffu, wD, hd);
        den += (whA + whB) + (whC + whD);
        // fp16 packed accumulate over this 4-edge group, then flush to fp32
        __half2 hacc[4];
        __half2 z2 = __float2half2_rn(0.f);
        hacc[0] = z2; hacc[1] = z2; hacc[2] = z2; hacc[3] = z2;
        hfma8(hacc, __float2half2_rn(whA), vA);
        hfma8(hacc, __float2half2_rn(whB), vB);
        hfma8(hacc, __float2half2_rn(whC), vC);
        hfma8(hacc, __float2half2_rn(whD), vD);
#pragma unroll
        for (int q = 0; q < 4; q++) {
            float2 f = __half22float2(hacc[q]);
            acc[2 * q] += f.x;
            acc[2 * q + 1] += f.y;
        }
    }
    for (; i < s1; i++) {
        int s = csrc[i];
        uint4 v = fb[(size_t)s * 32 + lane];
        float w = 0.f;
        if (lane < NHEAD) {
            float e = el[s * NHEAD + lane] + er8;
            e = e > 0.f ? e : 0.2f * e;
            w = __expf(e);
        }
        float wh = __shfl_sync(0xffffffffu, w, hd);
        den += wh;
        fma8(acc, wh, v);
    }

    float inv = den > 0.f ? 1.f / den : 0.f;
    float4 b0 = *(const float4*)(bias + 8 * lane);
    float4 b1 = *(const float4*)(bias + 8 * lane + 4);
    float o[8];
    o[0] = acc[0] * inv + b0.x; o[1] = acc[1] * inv + b0.y;
    o[2] = acc[2] * inv + b0.z; o[3] = acc[3] * inv + b0.w;
    o[4] = acc[4] * inv + b1.x; o[5] = acc[5] * inv + b1.y;
    o[6] = acc[6] * inv + b1.z; o[7] = acc[7] * inv + b1.w;
#pragma unroll
    for (int q = 0; q < 8; q++) o[q] = o[q] > 0.f ? o[q] : expm1f(o[q]);
    __half2 h0 = __floats2half2_rn(o[0], o[1]);
    __half2 h1 = __floats2half2_rn(o[2], o[3]);
    __half2 h2 = __floats2half2_rn(o[4], o[5]);
    __half2 h3 = __floats2half2_rn(o[6], o[7]);
    uint4 pk = make_uint4(*(uint32_t*)&h0, *(uint32_t*)&h1,
                          *(uint32_t*)&h2, *(uint32_t*)&h3);
    uint4* z = (uint4*)((p ? g_zh_b : g_zh_a) + (size_t)node * FF + 8 * lane);
    *z = pk;
}

// ---------------- K5: sem GEMM (f16 mma, K-chunked, occ>=2) -----------------
#define SPITCH 272
#define SG_A 0
#define SG_B 34816
#define SG_W 69632
#define SG_SMEM 70656

__global__ __launch_bounds__(256)
void sem_gemm_mma(const float* __restrict__ bsem, const float* __restrict__ wsem) {
    extern __shared__ char smb[];
    uint32_t sb = smem_u32(smb);
    int tid = threadIdx.x;
    int wid = tid >> 5, lane = tid & 31;
    int bm = blockIdx.x * 128;
    int path = blockIdx.y;
    const __half* A = path ? g_zh_b : g_zh_a;

    if (tid < SEMH) {
        ((float*)(smb + SG_W))[tid] = bsem[tid];
        ((float*)(smb + SG_W))[SEMH + tid] = wsem[tid];
    }

    int wm = wid & 3, wn = wid >> 2;
    float acc[2][8][4];
#pragma unroll
    for (int t = 0; t < 2; t++)
#pragma unroll
        for (int j = 0; j < 8; j++)
#pragma unroll
            for (int q = 0; q < 4; q++) acc[t][j][q] = 0.f;

    int a_row_off = (lane & 15);
    int a_k_off = (lane >> 4) << 3;
    int b_seg = lane >> 3;
    int b_n_off = (lane & 7) + ((b_seg >= 2) ? 8 : 0);
    int b_k_off = (b_seg & 1) << 3;

    for (int kc = 0; kc < 2; kc++) {
        if (kc) __syncthreads();   // prior chunk's LDSM reads complete
        {
            int row = tid >> 1;
            int half = (tid & 1) * 64;   // elems within chunk
            int gm = bm + row;
            bool valid = gm < NN;
            const uint4* src = (const uint4*)(A + (size_t)gm * FF + kc * 128 + half);
            uint4 zz = make_uint4(0, 0, 0, 0);
#pragma unroll
            for (int j = 0; j < 8; j++) {
                *(uint4*)(smb + SG_A + row * SPITCH + (half + j * 8) * 2) =
                    valid ? src[j] : zz;
            }
        }
        {
            int row = tid >> 1;
            int halfk = (tid & 1) * 64;
            const uint4* sh = (const uint4*)(g_wsemt + row * FF + kc * 128 + halfk);
#pragma unroll
            for (int j = 0; j < 8; j++) {
                *(uint4*)(smb + SG_B + row * SPITCH + (halfk + j * 8) * 2) = sh[j];
            }
        }
        __syncthreads();

#pragma unroll
        for (int k0 = 0; k0 < 128; k0 += 16) {
            uint32_t af[2][4];
#pragma unroll
            for (int t = 0; t < 2; t++) {
                int row = wm * 32 + t * 16 + a_row_off;
                uint32_t addr = sb + SG_A + row * SPITCH + (k0 + a_k_off) * 2;
                ldsm_x4(af[t][0], af[t][1], af[t][2], af[t][3], addr);
            }
            uint32_t bf[8][2];
#pragma unroll
            for (int j = 0; j < 8; j += 2) {
                int n = wn * 64 + j * 8 + b_n_off;
                uint32_t addr = sb + SG_B + n * SPITCH + (k0 + b_k_off) * 2;
                ldsm_x4(bf[j][0], bf[j][1], bf[j + 1][0], bf[j + 1][1], addr);
            }
#pragma unroll
            for (int t = 0; t < 2; t++)
#pragma unroll
                for (int j = 0; j < 8; j++) mma16816_f16(acc[t][j], af[t], bf[j]);
        }
    }

    const float* sbm = (const float*)(smb + SG_W);
    const float* swm = sbm + SEMH;
    int g = lane >> 2;
    int cq = (lane & 3) * 2;
    float part = 0.f;
#pragma unroll
    for (int t = 0; t < 2; t++) {
        int r0 = bm + wm * 32 + t * 16 + g;
        int r1 = r0 + 8;
#pragma unroll
        for (int j = 0; j < 8; j++) {
            int col = wn * 64 + j * 8 + cq;
            float b0 = sbm[col], b1 = sbm[col + 1];
            float w0 = swm[col], w1 = swm[col + 1];
            if (r0 < NN)
                part += tanh_fast(acc[t][j][0] + b0) * w0 +
                        tanh_fast(acc[t][j][1] + b1) * w1;
            if (r1 < NN)
                part += tanh_fast(acc[t][j][2] + b0) * w0 +
                        tanh_fast(acc[t][j][3] + b1) * w1;
        }
    }
#pragma unroll
    for (int o = 16; o > 0; o >>= 1) part += __shfl_xor_sync(0xffffffffu, part, o);
    __shared__ float warp_part[8];
    if (lane == 0) warp_part[wid] = part;
    __syncthreads();
    if (tid == 0) {
        float s = 0.f;
#pragma unroll
        for (int w = 0; w < 8; w++) s += warp_part[w];
        atomicAdd(&g_qsum[path], s);
    }
}

// ---------------- K6: final combine (beta fused, fp16 z inputs) -------------
__global__ void combine_kernel(float* __restrict__ out) {
    float qa = g_qsum[0] * (1.f / (float)NN);
    float qb = g_qsum[1] * (1.f / (float)NN);
    float m = fmaxf(qa, qb);
    float ea = __expf(qa - m), eb = __expf(qb - m);
    float inv = 1.f / (ea + eb);
    float b0 = ea * inv, b1 = eb * inv;
    int i0 = blockIdx.x * blockDim.x + threadIdx.x;
    int stride = gridDim.x * blockDim.x;
    const uint2* za = (const uint2*)g_zh_a;   // 4 halfs each
    const uint2* zb = (const uint2*)g_zh_b;
    float4* o = (float4*)out;
    for (int i = i0; i < NN * FF / 4; i += stride) {
        uint2 a = za[i];
        uint2 b = zb[i];
        float2 a0 = __half22float2(*(__half2*)&a.x);
        float2 a1 = __half22float2(*(__half2*)&a.y);
        float2 c0 = __half22float2(*(__half2*)&b.x);
        float2 c1 = __half22float2(*(__half2*)&b.y);
        float4 r;
        r.x = b0 * a0.x + b1 * c0.x;
        r.y = b0 * a0.y + b1 * c0.y;
        r.z = b0 * a1.x + b1 * c1.x;
        r.w = b0 * a1.y + b1 * c1.y;
        o[i] = r;
    }
}

// ---------------- launch ----------------------------------------------------
extern "C" void kernel_launch(void* const* d_in, const int* in_sizes, int n_in,
                              void* d_out, int out_size) {
    const float* h     = (const float*)d_in[0];
    const int* src_a   = (const int*)d_in[1];
    const int* dst_a   = (const int*)d_in[2];
    const int* src_b   = (const int*)d_in[3];
    const int* dst_b   = (const int*)d_in[4];
    const float* W_a   = (const float*)d_in[5];
    const float* al_a  = (const float*)d_in[6];
    const float* ar_a  = (const float*)d_in[7];
    const float* bias_a= (const float*)d_in[8];
    const float* W_b   = (const float*)d_in[9];
    const float* al_b  = (const float*)d_in[10];
    const float* ar_b  = (const float*)d_in[11];
    const float* bias_b= (const float*)d_in[12];
    const float* Wsem  = (const float*)d_in[13];
    const float* bsem  = (const float*)d_in[14];
    const float* wsem  = (const float*)d_in[15];
    float* out = (float*)d_out;

    cudaFuncSetAttribute(gemm_scatter_kernel, cudaFuncAttributeMaxDynamicSharedMemorySize, FG_SMEM);
    cudaFuncSetAttribute(sem_gemm_mma, cudaFuncAttributeMaxDynamicSharedMemorySize, SG_SMEM);

    hist_prep_kernel<<<HB + PB, 256>>>(dst_a, dst_b, h, W_a, W_b, Wsem);
    scan_kernel<<<2, 1024>>>();

    dim3 ggs(3, NB, 2);
    gemm_scatter_kernel<<<ggs, 256, FG_SMEM>>>(al_a, ar_a, al_b, ar_b,
                                               src_a, dst_a, src_b, dst_b);

    dim3 gagg((NN + 7) / 8, 2);
    agg_kernel<<<gagg, 256>>>(bias_a, bias_b);

    dim3 gsem(MT, 2);
    sem_gemm_mma<<<gsem, 256, SG_SMEM>>>(bsem, wsem);

    combine_kernel<<<2048, 256>>>(out);
}